// round 2
// baseline (speedup 1.0000x reference)
#include <cuda_runtime.h>
#include <math.h>

#define NUM_ENT 50000
#define NUM_RELS 200
#define D 200
#define NUM_EVT 20000
#define ROLE_NUM 20
#define RT_DIM 100
#define R_SLOTS 8
#define K_SLOTS 8
#define N_EDGES 800000
#define HALF_E 400000

// ---------------- scratch (device globals: no allocation allowed) ----------------
__device__ float g_role_proj[ROLE_NUM * D];
__device__ float g_ev_pre[NUM_EVT * D];
__device__ float g_ev_repr[NUM_EVT * D];
__device__ float g_ent_agg[NUM_ENT * D];
__device__ float g_x0[NUM_ENT * D];
__device__ float g_aggin[NUM_ENT * D];
__device__ float g_aggout[NUM_ENT * D];
__device__ int   g_cnt[2 * NUM_ENT];
__device__ int   g_off[2 * (NUM_ENT + 1)];
__device__ int   g_pos[2 * NUM_ENT];
__device__ int2  g_edges[N_EDGES];

// ---------------- CSR build ----------------

__global__ void zero_cnt_kernel() {
    int i = blockIdx.x * blockDim.x + threadIdx.x;
    int stride = gridDim.x * blockDim.x;
    for (; i < 2 * NUM_ENT; i += stride) g_cnt[i] = 0;
}

__global__ void count_edges_kernel(const int* __restrict__ ei) {
    const int* dst = ei + N_EDGES;
    int i = blockIdx.x * blockDim.x + threadIdx.x;
    int stride = gridDim.x * blockDim.x;
    for (; i < N_EDGES; i += stride) {
        int d = dst[i];
        int seg = (i < HALF_E) ? 0 : 1;
        atomicAdd(&g_cnt[seg * NUM_ENT + d], 1);
    }
}

// one block per segment (in / out); 1024 threads scan 50000 counts
__global__ void scan_kernel() {
    const int CH = 49;  // 1024*49 >= 50000
    int seg = blockIdx.x;
    const int* cnt = g_cnt + seg * NUM_ENT;
    int* off = g_off + seg * (NUM_ENT + 1);
    int* pos = g_pos + seg * NUM_ENT;
    __shared__ int s[1024];
    int t = threadIdx.x;
    int base = t * CH;
    int sum = 0;
    for (int j = 0; j < CH; j++) {
        int idx = base + j;
        if (idx < NUM_ENT) sum += cnt[idx];
    }
    s[t] = sum;
    __syncthreads();
    for (int o = 1; o < 1024; o <<= 1) {
        int v = (t >= o) ? s[t - o] : 0;
        __syncthreads();
        s[t] += v;
        __syncthreads();
    }
    int excl = s[t] - sum;
    int run = excl;
    for (int j = 0; j < CH; j++) {
        int idx = base + j;
        if (idx < NUM_ENT) {
            off[idx] = run;
            pos[idx] = run;
            run += cnt[idx];
        }
    }
    if (t == 1023) off[NUM_ENT] = s[1023];
}

__global__ void fill_edges_kernel(const int* __restrict__ ei, const int* __restrict__ et) {
    const int* src = ei;
    const int* dst = ei + N_EDGES;
    int i = blockIdx.x * blockDim.x + threadIdx.x;
    int stride = gridDim.x * blockDim.x;
    for (; i < N_EDGES; i += stride) {
        int seg = (i < HALF_E) ? 0 : 1;
        int d = dst[i];
        int p = atomicAdd(&g_pos[seg * NUM_ENT + d], 1);
        g_edges[seg * HALF_E + p] = make_int2(src[i], et[i]);
    }
}

// ---------------- EventConv pieces ----------------

// role_proj = role_type_embed @ W_role  (20 x 200)
__global__ void role_proj_kernel(const float* __restrict__ rte, const float* __restrict__ Wr) {
    __shared__ float row[RT_DIM];
    int r = blockIdx.x;
    int t = threadIdx.x;
    if (t < RT_DIM) row[t] = rte[r * RT_DIM + t];
    __syncthreads();
    if (t < D) {
        float acc = 0.f;
        #pragma unroll 4
        for (int k = 0; k < RT_DIM; k++) acc += row[k] * Wr[k * D + t];
        g_role_proj[r * D + t] = acc;
    }
}

// per-event masked-mean of gathered entity args composed with role projections
__global__ void event_agg_kernel(const float* __restrict__ init,
                                 const int* __restrict__ evi,
                                 const int* __restrict__ rt,
                                 const int* __restrict__ rm) {
    __shared__ int sIdx[R_SLOTS], sRt[R_SLOTS], sM[R_SLOTS];
    __shared__ float sden;
    int e = blockIdx.x;
    int t = threadIdx.x;
    if (t < R_SLOTS) {
        sIdx[t] = evi[t * NUM_EVT + e];
        sRt[t]  = rt[t * NUM_EVT + e];
        sM[t]   = rm[t * NUM_EVT + e];
    }
    __syncthreads();
    if (t == 0) {
        int s = 0;
        for (int r = 0; r < R_SLOTS; r++) s += sM[r];
        sden = 1.f / fmaxf((float)s, 1.f);
    }
    __syncthreads();
    if (t < D) {
        float acc = 0.f;
        #pragma unroll
        for (int r = 0; r < R_SLOTS; r++)
            if (sM[r]) acc += init[sIdx[r] * D + t] * g_role_proj[sRt[r] * D + t];
        g_ev_pre[e * D + t] = acc * sden;
    }
}

// per-entity masked-mean over event-slot gathers of ev_repr
__global__ void ent_agg_kernel(const int* __restrict__ eei, const int* __restrict__ em) {
    __shared__ int sIdx[K_SLOTS], sM[K_SLOTS];
    __shared__ float sden;
    int i = blockIdx.x;
    int t = threadIdx.x;
    if (t < K_SLOTS) {
        sIdx[t] = eei[t * NUM_ENT + i];
        sM[t]   = em[t * NUM_ENT + i];
    }
    __syncthreads();
    if (t == 0) {
        int s = 0;
        for (int k = 0; k < K_SLOTS; k++) s += sM[k];
        sden = 1.f / fmaxf((float)s, 1.f);
    }
    __syncthreads();
    if (t < D) {
        float acc = 0.f;
        #pragma unroll
        for (int k = 0; k < K_SLOTS; k++)
            if (sM[k]) acc += g_ev_repr[sIdx[k] * D + t];
        g_ent_agg[i * D + t] = acc * sden;
    }
}

// per-dst CSR gather of x0[src] - rel_embed[et], normalized by in-degree
__global__ void gather_agg_kernel(const float* __restrict__ rel, int seg,
                                  float* __restrict__ out) {
    int i = blockIdx.x;
    int t = threadIdx.x;
    const int* off = g_off + seg * (NUM_ENT + 1);
    int s0 = off[i], s1 = off[i + 1];
    int cnt = s1 - s0;
    __shared__ int2 se[256];
    float acc = 0.f;
    for (int base = s0; base < s1; base += 256) {
        int nb = min(256, s1 - base);
        if (t < nb) se[t] = g_edges[seg * HALF_E + base + t];
        __syncthreads();
        if (t < D) {
            for (int j = 0; j < nb; j++) {
                int2 e = se[j];
                acc += g_x0[e.x * D + t] - rel[e.y * D + t];
            }
        }
        __syncthreads();
    }
    if (t < D) out[i * D + t] = acc / fmaxf((float)cnt, 1.f);
}

// ---------------- fp32 GEMM, 128x64 tile, 8x4 register tile (FMA-bound) ----------------
// flags: bit0 = accumulate into C; bits[2:1] = epilogue (0 none, 1 tanh, 2 tanh(v/3+bias))
#define BM 128
#define BN 64
#define BK 8
__global__ void __launch_bounds__(256) sgemm_kernel(
    const float* __restrict__ A, const float* __restrict__ B, float* __restrict__ C,
    const float* __restrict__ add0, const float* __restrict__ a_sub,
    const float* __restrict__ bias, int M, int K, int N, int flags)
{
    __shared__ float As[BK][BM];
    __shared__ float Bs[BK][BN];
    int tid = threadIdx.x;
    int tx = tid & 15;      // 16 col groups of 4
    int ty = tid >> 4;      // 16 row groups of 8
    int row0 = blockIdx.y * BM;
    int col0 = blockIdx.x * BN;

    float acc[8][4];
    #pragma unroll
    for (int i = 0; i < 8; i++)
        #pragma unroll
        for (int j = 0; j < 4; j++) acc[i][j] = 0.f;

    for (int k0 = 0; k0 < K; k0 += BK) {
        // A tile: 128x8 = 1024 elems, 4 per thread
        #pragma unroll
        for (int i = 0; i < 4; i++) {
            int li = tid + i * 256;          // 0..1023
            int r = li >> 3, kk = li & 7;
            int m = row0 + r, k = k0 + kk;
            float a = 0.f;
            if (m < M && k < K) {
                a = A[m * K + k];
                if (a_sub) a -= a_sub[k];
            }
            As[kk][r] = a;
        }
        // B tile: 8x64 = 512 elems, 2 per thread
        #pragma unroll
        for (int i = 0; i < 2; i++) {
            int li = tid + i * 256;
            int kk = li >> 6, c = li & 63;
            int n = col0 + c, k = k0 + kk;
            Bs[kk][c] = (n < N && k < K) ? B[k * N + n] : 0.f;
        }
        __syncthreads();
        #pragma unroll
        for (int kk = 0; kk < BK; kk++) {
            float4 a0 = *(const float4*)&As[kk][ty * 8];
            float4 a1 = *(const float4*)&As[kk][ty * 8 + 4];
            float4 b4 = *(const float4*)&Bs[kk][tx * 4];
            float av[8] = {a0.x, a0.y, a0.z, a0.w, a1.x, a1.y, a1.z, a1.w};
            float bv[4] = {b4.x, b4.y, b4.z, b4.w};
            #pragma unroll
            for (int i = 0; i < 8; i++)
                #pragma unroll
                for (int j = 0; j < 4; j++)
                    acc[i][j] += av[i] * bv[j];
        }
        __syncthreads();
    }

    int epi = (flags >> 1) & 3;
    bool accC = flags & 1;
    #pragma unroll
    for (int i = 0; i < 8; i++) {
        int m = row0 + ty * 8 + i;
        if (m >= M) continue;
        #pragma unroll
        for (int j = 0; j < 4; j++) {
            int n = col0 + tx * 4 + j;
            if (n >= N) continue;
            float v = acc[i][j];
            if (accC) v += C[m * N + n];
            if (add0) v += add0[m * N + n];
            if (epi == 1) v = tanhf(v);
            else if (epi == 2) v = tanhf(v * (1.f / 3.f) + bias[n]);
            C[m * N + n] = v;
        }
    }
}

// ---------------- launch ----------------

static inline void launch_gemm(const float* A, const float* B, float* C,
                               const float* add0, const float* a_sub,
                               const float* bias, int M, int K, int flags) {
    dim3 grid((D + BN - 1) / BN, (M + BM - 1) / BM);
    sgemm_kernel<<<grid, 256>>>(A, B, C, add0, a_sub, bias, M, K, D, flags);
}

extern "C" void kernel_launch(void* const* d_in, const int* in_sizes, int n_in,
                              void* d_out, int out_size) {
    const float* init     = (const float*)d_in[0];
    const float* rel      = (const float*)d_in[1];
    const float* rte      = (const float*)d_in[2];
    const float* evemb    = (const float*)d_in[3];
    const float* evtype   = (const float*)d_in[4];
    const float* W_role   = (const float*)d_in[5];
    const float* W_type   = (const float*)d_in[6];
    const float* W_event  = (const float*)d_in[7];
    const float* W_self   = (const float*)d_in[8];
    const float* w_in     = (const float*)d_in[9];
    const float* w_out    = (const float*)d_in[10];
    const float* w_loop   = (const float*)d_in[11];
    const float* w_rel    = (const float*)d_in[12];
    const float* loop_rel = (const float*)d_in[13];
    const float* bias     = (const float*)d_in[14];
    const int* evi        = (const int*)d_in[15];
    const int* rt         = (const int*)d_in[16];
    const int* rm         = (const int*)d_in[17];
    const int* eei        = (const int*)d_in[18];
    const int* em         = (const int*)d_in[19];
    const int* ei         = (const int*)d_in[20];
    const int* et         = (const int*)d_in[21];

    float* outx = (float*)d_out;
    float* outr = outx + NUM_ENT * D;

    float *p_evpre, *p_evrepr, *p_entagg, *p_x0, *p_aggin, *p_aggout;
    cudaGetSymbolAddress((void**)&p_evpre,  g_ev_pre);
    cudaGetSymbolAddress((void**)&p_evrepr, g_ev_repr);
    cudaGetSymbolAddress((void**)&p_entagg, g_ent_agg);
    cudaGetSymbolAddress((void**)&p_x0,     g_x0);
    cudaGetSymbolAddress((void**)&p_aggin,  g_aggin);
    cudaGetSymbolAddress((void**)&p_aggout, g_aggout);

    // --- CSR build for edges (independent of embeddings, do it up front) ---
    zero_cnt_kernel<<<128, 256>>>();
    count_edges_kernel<<<512, 256>>>(ei);
    scan_kernel<<<2, 1024>>>();
    fill_edges_kernel<<<512, 256>>>(ei, et);

    // --- EventConv ---
    role_proj_kernel<<<ROLE_NUM, 256>>>(rte, W_role);
    event_agg_kernel<<<NUM_EVT, 256>>>(init, evi, rt, rm);                 // g_ev_pre = ev_agg
    launch_gemm(evtype, W_type, p_evpre, evemb, nullptr, nullptr,
                NUM_EVT, RT_DIM, /*ACC*/ 1);                               // += type_proj + event_embed
    launch_gemm(p_evpre, W_event, p_evrepr, nullptr, nullptr, nullptr,
                NUM_EVT, D, /*tanh*/ (1 << 1));                            // ev_repr
    ent_agg_kernel<<<NUM_ENT, 256>>>(eei, em);                             // g_ent_agg
    launch_gemm(init, W_self, p_x0, p_entagg, nullptr, nullptr,
                NUM_ENT, D, (1 << 1));                                     // x0 = tanh(init@W_self + ent_agg)

    // --- CompGCN ---
    gather_agg_kernel<<<NUM_ENT, 256>>>(rel, 0, p_aggin);
    gather_agg_kernel<<<NUM_ENT, 256>>>(rel, 1, p_aggout);
    launch_gemm(p_aggin,  w_in,   outx, nullptr, nullptr, nullptr, NUM_ENT, D, 0);
    launch_gemm(p_aggout, w_out,  outx, nullptr, nullptr, nullptr, NUM_ENT, D, 1);
    launch_gemm(p_x0,     w_loop, outx, nullptr, loop_rel, bias,
                NUM_ENT, D, 1 | (2 << 1));                                 // tanh((sum)/3 + bias)
    launch_gemm(rel, w_rel, outr, nullptr, nullptr, nullptr, 2 * NUM_RELS, D, 0);
}

// round 4
// speedup vs baseline: 1.5417x; 1.5417x over previous
#include <cuda_runtime.h>
#include <cuda_bf16.h>
#include <cstdint>
#include <math.h>

#define NUM_ENT 50000
#define NUM_RELS 200
#define D 200
#define NUM_EVT 20000
#define ROLE_NUM 20
#define RT_DIM 100
#define R_SLOTS 8
#define K_SLOTS 8
#define N_EDGES 800000
#define HALF_E 400000

#define KP1 128     // padded K for RT_DIM=100
#define KP2 256     // padded K for D=200
#define KP3 768     // concatenated K for the fused output GEMM (3 x 256)

// ---------------- scratch (device globals) ----------------
__device__ float    g_ev_agg[NUM_EVT * D];
__device__ float    g_ev_repr[NUM_EVT * D];
__device__ float    g_ent_agg[NUM_ENT * D];
__device__ float    g_x0[NUM_ENT * D];
__device__ float    g_role_proj[ROLE_NUM * D];
__device__ unsigned g_initA[NUM_ENT * KP2];        // split(init)
__device__ unsigned g_evtA[NUM_EVT * KP1];         // split(evt_type_emb)
__device__ unsigned g_evpreA[NUM_EVT * KP2];       // split(ev_pre)
__device__ unsigned g_catA[(size_t)NUM_ENT * KP3]; // [aggin | aggout | x0-loop_rel]
__device__ unsigned g_WtypeT[D * KP1];
__device__ unsigned g_WeventT[D * KP2];
__device__ unsigned g_WselfT[D * KP2];
__device__ unsigned g_B3T[D * KP3];                // [w_in ; w_out ; w_loop] transposed
__device__ int   g_cnt[2 * NUM_ENT];
__device__ int   g_off[2 * (NUM_ENT + 1)];
__device__ int   g_pos[2 * NUM_ENT];
__device__ int2  g_edges[N_EDGES];

// ---------------- helpers ----------------
__device__ __forceinline__ uint32_t smem_to_u32(const void* p) {
    uint32_t a;
    asm("{ .reg .u64 t; cvta.to.shared.u64 t, %1; cvt.u32.u64 %0, t; }" : "=r"(a) : "l"(p));
    return a;
}
// split fp32 -> packed (bf16 hi | bf16 lo << 16)
__device__ __forceinline__ unsigned pack_split(float v) {
    __nv_bfloat16 h = __float2bfloat16(v);
    float rf = v - __bfloat162float(h);
    __nv_bfloat16 l = __float2bfloat16(rf);
    return (unsigned)__bfloat16_as_ushort(h) | ((unsigned)__bfloat16_as_ushort(l) << 16);
}
__device__ __forceinline__ void ldsm_x4(uint32_t* r, uint32_t addr) {
    asm volatile("ldmatrix.sync.aligned.m8n8.x4.shared.b16 {%0,%1,%2,%3}, [%4];"
        : "=r"(r[0]), "=r"(r[1]), "=r"(r[2]), "=r"(r[3]) : "r"(addr));
}
__device__ __forceinline__ void mma_bf16(float* c, const uint32_t* a, uint32_t b0, uint32_t b1) {
    asm volatile("mma.sync.aligned.m16n8k16.row.col.f32.bf16.bf16.f32 "
        "{%0,%1,%2,%3}, {%4,%5,%6,%7}, {%8,%9}, {%0,%1,%2,%3};"
        : "+f"(c[0]), "+f"(c[1]), "+f"(c[2]), "+f"(c[3])
        : "r"(a[0]), "r"(a[1]), "r"(a[2]), "r"(a[3]), "r"(b0), "r"(b1));
}

// ---------------- CSR build ----------------
__global__ void zero_cnt_kernel() {
    int i = blockIdx.x * blockDim.x + threadIdx.x;
    int s = gridDim.x * blockDim.x;
    for (; i < 2 * NUM_ENT; i += s) g_cnt[i] = 0;
}
__global__ void count_edges_kernel(const int* __restrict__ ei) {
    const int* dst = ei + N_EDGES;
    int i = blockIdx.x * blockDim.x + threadIdx.x;
    int s = gridDim.x * blockDim.x;
    for (; i < N_EDGES; i += s) {
        int d = dst[i];
        int seg = (i < HALF_E) ? 0 : 1;
        atomicAdd(&g_cnt[seg * NUM_ENT + d], 1);
    }
}
__global__ void scan_kernel() {
    const int CH = 49;
    int seg = blockIdx.x;
    const int* cnt = g_cnt + seg * NUM_ENT;
    int* off = g_off + seg * (NUM_ENT + 1);
    int* pos = g_pos + seg * NUM_ENT;
    __shared__ int s[1024];
    int t = threadIdx.x;
    int base = t * CH;
    int sum = 0;
    for (int j = 0; j < CH; j++) { int idx = base + j; if (idx < NUM_ENT) sum += cnt[idx]; }
    s[t] = sum;
    __syncthreads();
    for (int o = 1; o < 1024; o <<= 1) {
        int v = (t >= o) ? s[t - o] : 0;
        __syncthreads();
        s[t] += v;
        __syncthreads();
    }
    int run = s[t] - sum;
    for (int j = 0; j < CH; j++) {
        int idx = base + j;
        if (idx < NUM_ENT) { off[idx] = run; pos[idx] = run; run += cnt[idx]; }
    }
    if (t == 1023) off[NUM_ENT] = s[1023];
}
__global__ void fill_edges_kernel(const int* __restrict__ ei, const int* __restrict__ et) {
    const int* src = ei;
    const int* dst = ei + N_EDGES;
    int i = blockIdx.x * blockDim.x + threadIdx.x;
    int s = gridDim.x * blockDim.x;
    for (; i < N_EDGES; i += s) {
        int seg = (i < HALF_E) ? 0 : 1;
        int d = dst[i];
        int p = atomicAdd(&g_pos[seg * NUM_ENT + d], 1);
        g_edges[seg * HALF_E + p] = make_int2(src[i], et[i]);
    }
}

// ---------------- conversions ----------------
__global__ void conv_split_kernel(const float* __restrict__ src, unsigned* __restrict__ dst,
                                  int K, int Kpad) {
    int m = blockIdx.x, t = threadIdx.x;
    if (t < Kpad) dst[(size_t)m * Kpad + t] = (t < K) ? pack_split(src[(size_t)m * K + t]) : 0u;
}
// weight W [K x D] -> transposed split dst[n*stride + off + k]
__global__ void conv_wt_kernel(const float* __restrict__ W, unsigned* __restrict__ dst,
                               int K, int Kseg, int stride, int off) {
    int n = blockIdx.x, t = threadIdx.x;
    if (t < Kseg) dst[(size_t)n * stride + off + t] = (t < K) ? pack_split(W[(size_t)t * D + n]) : 0u;
}

// ---------------- EventConv pieces ----------------
__global__ void role_proj_kernel(const float* __restrict__ rte, const float* __restrict__ Wr) {
    __shared__ float row[RT_DIM];
    int r = blockIdx.x, t = threadIdx.x;
    if (t < RT_DIM) row[t] = rte[r * RT_DIM + t];
    __syncthreads();
    if (t < D) {
        float acc = 0.f;
        #pragma unroll 4
        for (int k = 0; k < RT_DIM; k++) acc += row[k] * Wr[k * D + t];
        g_role_proj[r * D + t] = acc;
    }
}
__global__ void event_agg_kernel(const float* __restrict__ init, const int* __restrict__ evi,
                                 const int* __restrict__ rt, const int* __restrict__ rm) {
    __shared__ int sIdx[R_SLOTS], sRt[R_SLOTS], sM[R_SLOTS];
    __shared__ float sden;
    int e = blockIdx.x, t = threadIdx.x;
    if (t < R_SLOTS) { sIdx[t] = evi[t * NUM_EVT + e]; sRt[t] = rt[t * NUM_EVT + e]; sM[t] = rm[t * NUM_EVT + e]; }
    __syncthreads();
    if (t == 0) {
        int s = 0;
        for (int r = 0; r < R_SLOTS; r++) s += sM[r];
        sden = 1.f / fmaxf((float)s, 1.f);
    }
    __syncthreads();
    if (t < D) {
        float acc = 0.f;
        #pragma unroll
        for (int r = 0; r < R_SLOTS; r++)
            if (sM[r]) acc += init[sIdx[r] * D + t] * g_role_proj[sRt[r] * D + t];
        g_ev_agg[e * D + t] = acc * sden;
    }
}
__global__ void ent_agg_kernel(const int* __restrict__ eei, const int* __restrict__ em) {
    __shared__ int sIdx[K_SLOTS], sM[K_SLOTS];
    __shared__ float sden;
    int i = blockIdx.x, t = threadIdx.x;
    if (t < K_SLOTS) { sIdx[t] = eei[t * NUM_ENT + i]; sM[t] = em[t * NUM_ENT + i]; }
    __syncthreads();
    if (t == 0) {
        int s = 0;
        for (int k = 0; k < K_SLOTS; k++) s += sM[k];
        sden = 1.f / fmaxf((float)s, 1.f);
    }
    __syncthreads();
    if (t < D) {
        float acc = 0.f;
        #pragma unroll
        for (int k = 0; k < K_SLOTS; k++)
            if (sM[k]) acc += g_ev_repr[sIdx[k] * D + t];
        g_ent_agg[i * D + t] = acc * sden;
    }
}
// per-dst CSR gather -> packed split directly into concatenated A at column offset
__global__ void gather_agg_kernel(const float* __restrict__ rel, int seg, int colOff) {
    int i = blockIdx.x, t = threadIdx.x;
    const int* off = g_off + seg * (NUM_ENT + 1);
    int s0 = off[i], s1 = off[i + 1];
    int cnt = s1 - s0;
    __shared__ int2 se[256];
    float acc = 0.f;
    for (int base = s0; base < s1; base += 256) {
        int nb = min(256, s1 - base);
        if (t < nb) se[t] = g_edges[seg * HALF_E + base + t];
        __syncthreads();
        if (t < D) {
            for (int j = 0; j < nb; j++) {
                int2 e = se[j];
                acc += g_x0[e.x * D + t] - rel[e.y * D + t];
            }
        }
        __syncthreads();
    }
    if (t < D) g_catA[(size_t)i * KP3 + colOff + t] = pack_split(acc / fmaxf((float)cnt, 1.f));
}

// ---------------- warp-MMA split-bf16 GEMM: C(M x 200) = A(M x Kpad) @ Bt^T ----------------
// CTA tile 128 x 64, 8 warps of 32x32, BK = 32. smem row stride 80 B (conflict-free LDSM).
// modes: 0: v=C+add0+add1 -> split(outS) ; 1: outF=tanh(C)
//        2: v=tanh(C+add0) -> outF AND split(v - sub[n]) -> outS ; 3: outF=tanh(C/3+bias[n])
#define RSTB 80
__global__ void __launch_bounds__(256, 2) mma_gemm_kernel(
    const unsigned* __restrict__ A, int M, int Kpad,
    const unsigned* __restrict__ Bt, int mode,
    const float* __restrict__ add0, const float* __restrict__ add1,
    const float* __restrict__ sub, const float* __restrict__ bias,
    float* __restrict__ outF, unsigned* __restrict__ outS, int sStride, int sOff)
{
    __shared__ __align__(16) unsigned char sAhi[128 * RSTB];
    __shared__ __align__(16) unsigned char sAlo[128 * RSTB];
    __shared__ __align__(16) unsigned char sBhi[64 * RSTB];
    __shared__ __align__(16) unsigned char sBlo[64 * RSTB];

    int tid = threadIdx.x, wid = tid >> 5, lane = tid & 31;
    int wm = wid & 3, wn = wid >> 2;
    int row0 = blockIdx.x * 128, col0 = blockIdx.y * 64;

    uint32_t aHiB = smem_to_u32(sAhi), aLoB = smem_to_u32(sAlo);
    uint32_t bHiB = smem_to_u32(sBhi), bLoB = smem_to_u32(sBlo);

    float acc[2][4][4];
    #pragma unroll
    for (int i = 0; i < 2; i++)
        #pragma unroll
        for (int j = 0; j < 4; j++)
            #pragma unroll
            for (int k = 0; k < 4; k++) acc[i][j][k] = 0.f;

    int nCh = Kpad >> 5;
    for (int c = 0; c < nCh; c++) {
        // stage A: 128 rows x 32 packed u32 (8 uint4 per row), 4 uint4 per thread
        #pragma unroll
        for (int i = 0; i < 4; i++) {
            int v = tid + i * 256;          // 0..1023
            int r = v >> 3, j = v & 7;
            uint4 d = make_uint4(0u, 0u, 0u, 0u);
            if (row0 + r < M)
                d = *(const uint4*)(A + (size_t)(row0 + r) * Kpad + c * 32 + j * 4);
            unsigned h0 = (d.x & 0xffffu) | (d.y << 16);
            unsigned h1 = (d.z & 0xffffu) | (d.w << 16);
            unsigned l0 = (d.x >> 16) | (d.y & 0xffff0000u);
            unsigned l1 = (d.z >> 16) | (d.w & 0xffff0000u);
            *(uint2*)(sAhi + r * RSTB + j * 8) = make_uint2(h0, h1);
            *(uint2*)(sAlo + r * RSTB + j * 8) = make_uint2(l0, l1);
        }
        // stage B: 64 rows x 32 packed, 2 uint4 per thread
        #pragma unroll
        for (int i = 0; i < 2; i++) {
            int v = tid + i * 256;          // 0..511
            int r = v >> 3, j = v & 7;
            uint4 d = make_uint4(0u, 0u, 0u, 0u);
            if (col0 + r < D)
                d = *(const uint4*)(Bt + (size_t)(col0 + r) * Kpad + c * 32 + j * 4);
            unsigned h0 = (d.x & 0xffffu) | (d.y << 16);
            unsigned h1 = (d.z & 0xffffu) | (d.w << 16);
            unsigned l0 = (d.x >> 16) | (d.y & 0xffff0000u);
            unsigned l1 = (d.z >> 16) | (d.w & 0xffff0000u);
            *(uint2*)(sBhi + r * RSTB + j * 8) = make_uint2(h0, h1);
            *(uint2*)(sBlo + r * RSTB + j * 8) = make_uint2(l0, l1);
        }
        __syncthreads();

        #pragma unroll
        for (int ks = 0; ks < 2; ks++) {
            uint32_t ahi[2][4], alo[2][4], bhi[2][4], blo[2][4];
            int arow = wm * 32 + (lane & 15);
            int aoff = ks * 32 + (lane >> 4) * 16;
            #pragma unroll
            for (int mt = 0; mt < 2; mt++) {
                uint32_t ad = (arow + mt * 16) * RSTB + aoff;
                ldsm_x4(ahi[mt], aHiB + ad);
                ldsm_x4(alo[mt], aLoB + ad);
            }
            int brow = wn * 32 + ((lane >> 4) << 3) + (lane & 7);
            int boff = ks * 32 + (((lane >> 3) & 1) << 4);
            #pragma unroll
            for (int nb = 0; nb < 2; nb++) {
                uint32_t bd = (brow + nb * 16) * RSTB + boff;
                ldsm_x4(bhi[nb], bHiB + bd);
                ldsm_x4(blo[nb], bLoB + bd);
            }
            #pragma unroll
            for (int mt = 0; mt < 2; mt++)
                #pragma unroll
                for (int nt = 0; nt < 4; nt++) {
                    int x4 = nt >> 1, pr = (nt & 1) << 1;
                    mma_bf16(acc[mt][nt], ahi[mt], bhi[x4][pr], bhi[x4][pr + 1]);
                    mma_bf16(acc[mt][nt], ahi[mt], blo[x4][pr], blo[x4][pr + 1]);
                    mma_bf16(acc[mt][nt], alo[mt], bhi[x4][pr], bhi[x4][pr + 1]);
                }
        }
        __syncthreads();
    }

    // ---- epilogue from register accumulators ----
    int g = lane >> 2, tg = lane & 3;
    #pragma unroll
    for (int mt = 0; mt < 2; mt++)
        #pragma unroll
        for (int nt = 0; nt < 4; nt++) {
            int n = col0 + wn * 32 + nt * 8 + tg * 2;
            if (n >= D) continue;
            #pragma unroll
            for (int hh = 0; hh < 2; hh++) {
                int m = row0 + wm * 32 + mt * 16 + g + hh * 8;
                if (m >= M) continue;
                float d0 = acc[mt][nt][2 * hh], d1 = acc[mt][nt][2 * hh + 1];
                size_t p = (size_t)m * D + n;
                if (mode == 0) {
                    float v0 = d0 + add0[p] + add1[p];
                    float v1 = d1 + add0[p + 1] + add1[p + 1];
                    *(uint2*)(outS + (size_t)m * sStride + sOff + n) =
                        make_uint2(pack_split(v0), pack_split(v1));
                } else if (mode == 1) {
                    *(float2*)(outF + p) = make_float2(tanhf(d0), tanhf(d1));
                } else if (mode == 2) {
                    float v0 = tanhf(d0 + add0[p]);
                    float v1 = tanhf(d1 + add0[p + 1]);
                    *(float2*)(outF + p) = make_float2(v0, v1);
                    *(uint2*)(outS + (size_t)m * sStride + sOff + n) =
                        make_uint2(pack_split(v0 - sub[n]), pack_split(v1 - sub[n + 1]));
                } else {
                    *(float2*)(outF + p) = make_float2(tanhf(d0 * (1.f / 3.f) + bias[n]),
                                                        tanhf(d1 * (1.f / 3.f) + bias[n + 1]));
                }
            }
        }
}

// ---------------- small exact fp32 GEMM for r = rel_embed @ w_rel ----------------
__global__ void __launch_bounds__(256) sgemm_small_kernel(
    const float* __restrict__ A, const float* __restrict__ B, float* __restrict__ C, int M)
{
    int n = blockIdx.x * 64 + (threadIdx.x & 63);
    int m = blockIdx.y * 4 + (threadIdx.x >> 6);
    if (m >= M || n >= D) return;
    float acc = 0.f;
    for (int k = 0; k < D; k++) acc += A[m * D + k] * B[k * D + n];
    C[m * D + n] = acc;
}

// ---------------- launch ----------------
extern "C" void kernel_launch(void* const* d_in, const int* in_sizes, int n_in,
                              void* d_out, int out_size) {
    const float* init     = (const float*)d_in[0];
    const float* rel      = (const float*)d_in[1];
    const float* rte      = (const float*)d_in[2];
    const float* evemb    = (const float*)d_in[3];
    const float* evtype   = (const float*)d_in[4];
    const float* W_role   = (const float*)d_in[5];
    const float* W_type   = (const float*)d_in[6];
    const float* W_event  = (const float*)d_in[7];
    const float* W_self   = (const float*)d_in[8];
    const float* w_in     = (const float*)d_in[9];
    const float* w_out    = (const float*)d_in[10];
    const float* w_loop   = (const float*)d_in[11];
    const float* w_rel    = (const float*)d_in[12];
    const float* loop_rel = (const float*)d_in[13];
    const float* bias     = (const float*)d_in[14];
    const int* evi        = (const int*)d_in[15];
    const int* rt         = (const int*)d_in[16];
    const int* rm         = (const int*)d_in[17];
    const int* eei        = (const int*)d_in[18];
    const int* em         = (const int*)d_in[19];
    const int* ei         = (const int*)d_in[20];
    const int* et         = (const int*)d_in[21];

    float* outx = (float*)d_out;
    float* outr = outx + (size_t)NUM_ENT * D;

    float *p_evagg, *p_evrepr, *p_entagg, *p_x0;
    unsigned *p_initA, *p_evtA, *p_evpreA, *p_catA, *p_WtT, *p_WeT, *p_WsT, *p_B3T;
    cudaGetSymbolAddress((void**)&p_evagg,  g_ev_agg);
    cudaGetSymbolAddress((void**)&p_evrepr, g_ev_repr);
    cudaGetSymbolAddress((void**)&p_entagg, g_ent_agg);
    cudaGetSymbolAddress((void**)&p_x0,     g_x0);
    cudaGetSymbolAddress((void**)&p_initA,  g_initA);
    cudaGetSymbolAddress((void**)&p_evtA,   g_evtA);
    cudaGetSymbolAddress((void**)&p_evpreA, g_evpreA);
    cudaGetSymbolAddress((void**)&p_catA,   g_catA);
    cudaGetSymbolAddress((void**)&p_WtT,    g_WtypeT);
    cudaGetSymbolAddress((void**)&p_WeT,    g_WeventT);
    cudaGetSymbolAddress((void**)&p_WsT,    g_WselfT);
    cudaGetSymbolAddress((void**)&p_B3T,    g_B3T);

    // CSR build
    zero_cnt_kernel<<<128, 256>>>();
    count_edges_kernel<<<512, 256>>>(ei);
    scan_kernel<<<2, 1024>>>();
    fill_edges_kernel<<<512, 256>>>(ei, et);

    // operand conversions
    conv_split_kernel<<<NUM_ENT, 256>>>(init,   p_initA, D,      KP2);
    conv_split_kernel<<<NUM_EVT, 256>>>(evtype, p_evtA,  RT_DIM, KP1);
    conv_wt_kernel<<<D, 256>>>(W_type,  p_WtT, RT_DIM, KP1, KP1, 0);
    conv_wt_kernel<<<D, 256>>>(W_event, p_WeT, D, KP2, KP2, 0);
    conv_wt_kernel<<<D, 256>>>(W_self,  p_WsT, D, KP2, KP2, 0);
    conv_wt_kernel<<<D, 256>>>(w_in,    p_B3T, D, KP2, KP3, 0);
    conv_wt_kernel<<<D, 256>>>(w_out,   p_B3T, D, KP2, KP3, KP2);
    conv_wt_kernel<<<D, 256>>>(w_loop,  p_B3T, D, KP2, KP3, 2 * KP2);

    // EventConv
    role_proj_kernel<<<ROLE_NUM, 256>>>(rte, W_role);
    event_agg_kernel<<<NUM_EVT, 256>>>(init, evi, rt, rm);
    // E1: ev_pre = evtype @ W_type + ev_agg + evemb -> split
    mma_gemm_kernel<<<dim3((NUM_EVT + 127) / 128, 4), 256>>>(
        p_evtA, NUM_EVT, KP1, p_WtT, 0, p_evagg, evemb, nullptr, nullptr,
        nullptr, p_evpreA, KP2, 0);
    // E2: ev_repr = tanh(ev_pre @ W_event)
    mma_gemm_kernel<<<dim3((NUM_EVT + 127) / 128, 4), 256>>>(
        p_evpreA, NUM_EVT, KP2, p_WeT, 1, nullptr, nullptr, nullptr, nullptr,
        p_evrepr, nullptr, 0, 0);
    ent_agg_kernel<<<NUM_ENT, 256>>>(eei, em);
    // SELF: x0 = tanh(init @ W_self + ent_agg); also split(x0 - loop_rel) -> catA seg2
    mma_gemm_kernel<<<dim3((NUM_ENT + 127) / 128, 4), 256>>>(
        p_initA, NUM_ENT, KP2, p_WsT, 2, p_entagg, nullptr, loop_rel, nullptr,
        p_x0, p_catA, KP3, 2 * KP2);

    // CompGCN gathers -> catA seg0/seg1
    gather_agg_kernel<<<NUM_ENT, 256>>>(rel, 0, 0);
    gather_agg_kernel<<<NUM_ENT, 256>>>(rel, 1, KP2);
    // fused output GEMM: outx = tanh((catA @ B3)/3 + bias)
    mma_gemm_kernel<<<dim3((NUM_ENT + 127) / 128, 4), 256>>>(
        p_catA, NUM_ENT, KP3, p_B3T, 3, nullptr, nullptr, nullptr, bias,
        outx, nullptr, 0, 0);

    // r = rel_embed @ w_rel (exact fp32, tiny)
    {
        dim3 grid((D + 63) / 64, (2 * NUM_RELS + 3) / 4);
        sgemm_small_kernel<<<grid, 256>>>(rel, w_rel, outr, 2 * NUM_RELS);
    }
}

// round 7
// speedup vs baseline: 1.6006x; 1.0382x over previous
#include <cuda_runtime.h>
#include <cuda_bf16.h>
#include <cstdint>
#include <math.h>

#define NUM_ENT 50000
#define NUM_RELS 200
#define D 200
#define NUM_EVT 20000
#define ROLE_NUM 20
#define RT_DIM 100
#define R_SLOTS 8
#define K_SLOTS 8
#define N_EDGES 800000
#define HALF_E 400000

#define KP1 128     // padded K for RT_DIM=100
#define KP2 224     // padded K for D=200 (7 x 32)
#define KP3 672     // concatenated K for fused output GEMM (3 x 224)

typedef __nv_bfloat16 bf16;

// ---------------- scratch (device globals; 16B-aligned for vector access) -----
__device__ __align__(16) float g_ev_agg[NUM_EVT * D];
__device__ __align__(16) float g_ev_repr[NUM_EVT * D];
__device__ __align__(16) float g_ent_agg[NUM_ENT * D];
__device__ __align__(16) float g_x0[NUM_ENT * D];
__device__ __align__(16) float g_role_proj[ROLE_NUM * D];
__device__ __align__(16) bf16  g_initH[NUM_ENT * KP2];
__device__ __align__(16) bf16  g_initL[NUM_ENT * KP2];
__device__ __align__(16) bf16  g_evtH[NUM_EVT * KP1];
__device__ __align__(16) bf16  g_evtL[NUM_EVT * KP1];
__device__ __align__(16) bf16  g_evpreH[NUM_EVT * KP2];
__device__ __align__(16) bf16  g_evpreL[NUM_EVT * KP2];
__device__ __align__(16) bf16  g_catH[(size_t)NUM_ENT * KP3];
__device__ __align__(16) bf16  g_catL[(size_t)NUM_ENT * KP3];
__device__ __align__(16) bf16  g_WtH[D * KP1];
__device__ __align__(16) bf16  g_WtL[D * KP1];
__device__ __align__(16) bf16  g_WeH[D * KP2];
__device__ __align__(16) bf16  g_WeL[D * KP2];
__device__ __align__(16) bf16  g_WsH[D * KP2];
__device__ __align__(16) bf16  g_WsL[D * KP2];
__device__ __align__(16) bf16  g_B3H[D * KP3];
__device__ __align__(16) bf16  g_B3L[D * KP3];
__device__ int   g_cnt[2 * NUM_ENT];
__device__ int   g_off[2 * (NUM_ENT + 1)];
__device__ int   g_pos[2 * NUM_ENT];
__device__ __align__(16) int2  g_edges[N_EDGES];

// ---------------- helpers ----------------
__device__ __forceinline__ uint32_t smem_to_u32(const void* p) {
    uint32_t a;
    asm("{ .reg .u64 t; cvta.to.shared.u64 t, %1; cvt.u32.u64 %0, t; }" : "=r"(a) : "l"(p));
    return a;
}
__device__ __forceinline__ void split2(float v, bf16& h, bf16& l) {
    h = __float2bfloat16(v);
    l = __float2bfloat16(v - __bfloat162float(h));
}
__device__ __forceinline__ void ldsm_x4(uint32_t* r, uint32_t addr) {
    asm volatile("ldmatrix.sync.aligned.m8n8.x4.shared.b16 {%0,%1,%2,%3}, [%4];"
        : "=r"(r[0]), "=r"(r[1]), "=r"(r[2]), "=r"(r[3]) : "r"(addr));
}
__device__ __forceinline__ void mma_bf16(float* c, const uint32_t* a, uint32_t b0, uint32_t b1) {
    asm volatile("mma.sync.aligned.m16n8k16.row.col.f32.bf16.bf16.f32 "
        "{%0,%1,%2,%3}, {%4,%5,%6,%7}, {%8,%9}, {%0,%1,%2,%3};"
        : "+f"(c[0]), "+f"(c[1]), "+f"(c[2]), "+f"(c[3])
        : "r"(a[0]), "r"(a[1]), "r"(a[2]), "r"(a[3]), "r"(b0), "r"(b1));
}

// ---------------- CSR build ----------------
__global__ void zero_cnt_kernel() {
    int i = blockIdx.x * blockDim.x + threadIdx.x;
    int s = gridDim.x * blockDim.x;
    for (; i < 2 * NUM_ENT; i += s) g_cnt[i] = 0;
}
__global__ void count_edges_kernel(const int* __restrict__ ei) {
    const int* dst = ei + N_EDGES;
    int i = blockIdx.x * blockDim.x + threadIdx.x;
    int s = gridDim.x * blockDim.x;
    for (; i < N_EDGES; i += s) {
        int d = dst[i];
        int seg = (i < HALF_E) ? 0 : 1;
        atomicAdd(&g_cnt[seg * NUM_ENT + d], 1);
    }
}
__global__ void scan_kernel() {
    const int CH = 49;
    int seg = blockIdx.x;
    const int* cnt = g_cnt + seg * NUM_ENT;
    int* off = g_off + seg * (NUM_ENT + 1);
    int* pos = g_pos + seg * NUM_ENT;
    __shared__ int s[1024];
    int t = threadIdx.x;
    int base = t * CH;
    int sum = 0;
    for (int j = 0; j < CH; j++) { int idx = base + j; if (idx < NUM_ENT) sum += cnt[idx]; }
    s[t] = sum;
    __syncthreads();
    for (int o = 1; o < 1024; o <<= 1) {
        int v = (t >= o) ? s[t - o] : 0;
        __syncthreads();
        s[t] += v;
        __syncthreads();
    }
    int run = s[t] - sum;
    for (int j = 0; j < CH; j++) {
        int idx = base + j;
        if (idx < NUM_ENT) { off[idx] = run; pos[idx] = run; run += cnt[idx]; }
    }
    if (t == 1023) off[NUM_ENT] = s[1023];
}
__global__ void fill_edges_kernel(const int* __restrict__ ei, const int* __restrict__ et) {
    const int* src = ei;
    const int* dst = ei + N_EDGES;
    int i = blockIdx.x * blockDim.x + threadIdx.x;
    int s = gridDim.x * blockDim.x;
    for (; i < N_EDGES; i += s) {
        int seg = (i < HALF_E) ? 0 : 1;
        int d = dst[i];
        int p = atomicAdd(&g_pos[seg * NUM_ENT + d], 1);
        g_edges[seg * HALF_E + p] = make_int2(src[i], et[i]);
    }
}

// ---------------- conversions ----------------
__global__ void conv_split_kernel(const float* __restrict__ src, bf16* __restrict__ h,
                                  bf16* __restrict__ l, int K, int Kpad) {
    int m = blockIdx.x, t = threadIdx.x;
    if (t < Kpad) {
        float v = (t < K) ? src[(size_t)m * K + t] : 0.f;
        bf16 hh, ll;
        split2(v, hh, ll);
        h[(size_t)m * Kpad + t] = hh;
        l[(size_t)m * Kpad + t] = ll;
    }
}
// W [K x D] -> transposed split dst[n*stride + off + k]
__global__ void conv_wt_kernel(const float* __restrict__ W, bf16* __restrict__ h,
                               bf16* __restrict__ l, int K, int Kseg, int stride, int off) {
    int n = blockIdx.x, t = threadIdx.x;
    if (t < Kseg) {
        float v = (t < K) ? W[(size_t)t * D + n] : 0.f;
        bf16 hh, ll;
        split2(v, hh, ll);
        h[(size_t)n * stride + off + t] = hh;
        l[(size_t)n * stride + off + t] = ll;
    }
}

// ---------------- EventConv pieces ----------------
__global__ void role_proj_kernel(const float* __restrict__ rte, const float* __restrict__ Wr) {
    __shared__ float row[RT_DIM];
    int r = blockIdx.x, t = threadIdx.x;
    if (t < RT_DIM) row[t] = rte[r * RT_DIM + t];
    __syncthreads();
    if (t < D) {
        float acc = 0.f;
        #pragma unroll 4
        for (int k = 0; k < RT_DIM; k++) acc += row[k] * Wr[k * D + t];
        g_role_proj[r * D + t] = acc;
    }
}
__global__ void event_agg_kernel(const float* __restrict__ init, const int* __restrict__ evi,
                                 const int* __restrict__ rt, const int* __restrict__ rm) {
    __shared__ int sIdx[R_SLOTS], sRt[R_SLOTS], sM[R_SLOTS];
    __shared__ float sden;
    int e = blockIdx.x, t = threadIdx.x;
    if (t < R_SLOTS) { sIdx[t] = evi[t * NUM_EVT + e]; sRt[t] = rt[t * NUM_EVT + e]; sM[t] = rm[t * NUM_EVT + e]; }
    __syncthreads();
    if (t == 0) {
        int s = 0;
        for (int r = 0; r < R_SLOTS; r++) s += sM[r];
        sden = 1.f / fmaxf((float)s, 1.f);
    }
    __syncthreads();
    if (t < D) {
        float acc = 0.f;
        #pragma unroll
        for (int r = 0; r < R_SLOTS; r++)
            if (sM[r]) acc += init[sIdx[r] * D + t] * g_role_proj[sRt[r] * D + t];
        g_ev_agg[e * D + t] = acc * sden;
    }
}
__global__ void ent_agg_kernel(const int* __restrict__ eei, const int* __restrict__ em) {
    __shared__ int sIdx[K_SLOTS], sM[K_SLOTS];
    __shared__ float sden;
    int i = blockIdx.x, t = threadIdx.x;
    if (t < K_SLOTS) { sIdx[t] = eei[t * NUM_ENT + i]; sM[t] = em[t * NUM_ENT + i]; }
    __syncthreads();
    if (t == 0) {
        int s = 0;
        for (int k = 0; k < K_SLOTS; k++) s += sM[k];
        sden = 1.f / fmaxf((float)s, 1.f);
    }
    __syncthreads();
    if (t < D) {
        float acc = 0.f;
        #pragma unroll
        for (int k = 0; k < K_SLOTS; k++)
            if (sM[k]) acc += g_ev_repr[sIdx[k] * D + t];
        g_ent_agg[i * D + t] = acc * sden;
    }
}
// per-dst CSR gather -> split(mean) into g_cat at column offset
__global__ void gather_agg_kernel(const float* __restrict__ rel, int seg, int colOff) {
    int i = blockIdx.x, t = threadIdx.x;
    const int* off = g_off + seg * (NUM_ENT + 1);
    int s0 = off[i], s1 = off[i + 1];
    int cnt = s1 - s0;
    __shared__ int2 se[256];
    float acc = 0.f;
    for (int base = s0; base < s1; base += 256) {
        int nb = min(256, s1 - base);
        if (t < nb) se[t] = g_edges[seg * HALF_E + base + t];
        __syncthreads();
        if (t < D) {
            for (int j = 0; j < nb; j++) {
                int2 e = se[j];
                acc += g_x0[e.x * D + t] - rel[e.y * D + t];
            }
        }
        __syncthreads();
    }
    if (t < D) {
        float v = acc / fmaxf((float)cnt, 1.f);
        bf16 hh, ll;
        split2(v, hh, ll);
        g_catH[(size_t)i * KP3 + colOff + t] = hh;
        g_catL[(size_t)i * KP3 + colOff + t] = ll;
    }
}

// ---------------- warp-MMA split-bf16 GEMM: C(M x 200) = A(M x Kp) @ Bt^T -------------
// CTA tile 64 x 256 (full output width -> A read exactly once), 8 warps 2x4
// (warp tile 32x64), BK=32, synchronous staging (single stage).
// smem row stride 80 B (conflict-free ldmatrix).
// modes: 0: v=C+add0+add1 -> split(outH/L) ; 1: outF=tanh(C)
//        2: v=tanh(C+add0) -> outF AND split(v - sub[n]) -> outH/L ; 3: outF=tanh(C/3+bias[n])
#define RST 80
#define SA_B (64 * RST)      // 5120
#define SB_B (256 * RST)     // 20480
#define OFF_AH 0
#define OFF_AL SA_B
#define OFF_BH (2 * SA_B)
#define OFF_BL (2 * SA_B + SB_B)
#define SMEM_TOT (2 * SA_B + 2 * SB_B)   // 51200
__global__ void __launch_bounds__(256) mma_gemm_kernel(
    const bf16* __restrict__ AH, const bf16* __restrict__ AL, int M, int Kp,
    const bf16* __restrict__ BH, const bf16* __restrict__ BL, int mode,
    const float* __restrict__ add0, const float* __restrict__ add1,
    const float* __restrict__ sub, const float* __restrict__ bias,
    float* __restrict__ outF, bf16* __restrict__ outH, bf16* __restrict__ outL,
    int sStride, int sOff)
{
    extern __shared__ __align__(16) unsigned char dsm[];
    uint32_t sb = smem_to_u32(dsm);
    int tid = threadIdx.x, wid = tid >> 5, lane = tid & 31;
    int wm = wid & 1, wn = wid >> 1;
    int row0 = blockIdx.x * 64;

    float acc[2][8][4];
    #pragma unroll
    for (int i = 0; i < 2; i++)
        #pragma unroll
        for (int j = 0; j < 8; j++)
            #pragma unroll
            for (int k = 0; k < 4; k++) acc[i][j][k] = 0.f;

    // staging thread mapping: A 64 rows x 4 quads; B 256 rows x 4 quads (x4 iters)
    int ar = tid >> 2, aq = tid & 3;
    bool apred = (row0 + ar) < M;
    size_t arow = apred ? (size_t)(row0 + ar) : 0;
    int nCh = Kp >> 5;

    for (int c = 0; c < nCh; c++) {
        // A: hi + lo (16B per quad)
        {
            uint4 dh = make_uint4(0, 0, 0, 0), dl = make_uint4(0, 0, 0, 0);
            if (apred) {
                dh = *(const uint4*)(AH + arow * Kp + c * 32 + aq * 8);
                dl = *(const uint4*)(AL + arow * Kp + c * 32 + aq * 8);
            }
            *(uint4*)(dsm + OFF_AH + ar * RST + aq * 16) = dh;
            *(uint4*)(dsm + OFF_AL + ar * RST + aq * 16) = dl;
        }
        // B: 1024 quads per array, 4 per thread
        #pragma unroll
        for (int i = 0; i < 4; i++) {
            int v = tid + i * 256;
            int br = v >> 2, bq = v & 3;
            uint4 dh = make_uint4(0, 0, 0, 0), dl = make_uint4(0, 0, 0, 0);
            if (br < D) {
                dh = *(const uint4*)(BH + (size_t)br * Kp + c * 32 + bq * 8);
                dl = *(const uint4*)(BL + (size_t)br * Kp + c * 32 + bq * 8);
            }
            *(uint4*)(dsm + OFF_BH + br * RST + bq * 16) = dh;
            *(uint4*)(dsm + OFF_BL + br * RST + bq * 16) = dl;
        }
        __syncthreads();

        uint32_t aH = sb + OFF_AH, aL = sb + OFF_AL;
        uint32_t bH = sb + OFF_BH, bL = sb + OFF_BL;
        #pragma unroll
        for (int ks = 0; ks < 2; ks++) {
            uint32_t ahi[2][4], alo[2][4];
            int arw = wm * 32 + (lane & 15);
            int aof = ks * 32 + (lane >> 4) * 16;
            #pragma unroll
            for (int mt = 0; mt < 2; mt++) {
                uint32_t ad = (arw + mt * 16) * RST + aof;
                ldsm_x4(ahi[mt], aH + ad);
                ldsm_x4(alo[mt], aL + ad);
            }
            #pragma unroll
            for (int nq = 0; nq < 4; nq++) {
                uint32_t bhi[4], blo[4];
                int brw = wn * 64 + nq * 16 + ((lane >> 4) << 3) + (lane & 7);
                int bof = ks * 32 + (((lane >> 3) & 1) << 4);
                uint32_t bd = brw * RST + bof;
                ldsm_x4(bhi, bH + bd);
                ldsm_x4(blo, bL + bd);
                #pragma unroll
                for (int sub2 = 0; sub2 < 2; sub2++) {
                    int nt = nq * 2 + sub2, pr = sub2 * 2;
                    #pragma unroll
                    for (int mt = 0; mt < 2; mt++) {
                        mma_bf16(acc[mt][nt], ahi[mt], bhi[pr], bhi[pr + 1]);
                        mma_bf16(acc[mt][nt], ahi[mt], blo[pr], blo[pr + 1]);
                        mma_bf16(acc[mt][nt], alo[mt], bhi[pr], bhi[pr + 1]);
                    }
                }
            }
        }
        __syncthreads();
    }

    // ---- epilogue ----
    int g = lane >> 2, tg = lane & 3;
    #pragma unroll
    for (int mt = 0; mt < 2; mt++)
        #pragma unroll
        for (int nt = 0; nt < 8; nt++) {
            int n = wn * 64 + nt * 8 + tg * 2;
            if (n >= D) continue;
            #pragma unroll
            for (int hh = 0; hh < 2; hh++) {
                int m = row0 + wm * 32 + mt * 16 + g + hh * 8;
                if (m >= M) continue;
                float d0 = acc[mt][nt][2 * hh], d1 = acc[mt][nt][2 * hh + 1];
                size_t p = (size_t)m * D + n;
                if (mode == 0) {
                    float v0 = d0 + add0[p] + add1[p];
                    float v1 = d1 + add0[p + 1] + add1[p + 1];
                    bf16 h0, l0, h1, l1;
                    split2(v0, h0, l0);
                    split2(v1, h1, l1);
                    size_t q = (size_t)m * sStride + sOff + n;
                    outH[q] = h0; outH[q + 1] = h1;
                    outL[q] = l0; outL[q + 1] = l1;
                } else if (mode == 1) {
                    *(float2*)(outF + p) = make_float2(tanhf(d0), tanhf(d1));
                } else if (mode == 2) {
                    float v0 = tanhf(d0 + add0[p]);
                    float v1 = tanhf(d1 + add0[p + 1]);
                    *(float2*)(outF + p) = make_float2(v0, v1);
                    bf16 h0, l0, h1, l1;
                    split2(v0 - sub[n], h0, l0);
                    split2(v1 - sub[n + 1], h1, l1);
                    size_t q = (size_t)m * sStride + sOff + n;
                    outH[q] = h0; outH[q + 1] = h1;
                    outL[q] = l0; outL[q + 1] = l1;
                } else {
                    *(float2*)(outF + p) = make_float2(tanhf(d0 * (1.f / 3.f) + bias[n]),
                                                        tanhf(d1 * (1.f / 3.f) + bias[n + 1]));
                }
            }
        }
}

// ---------------- small exact fp32 GEMM for r = rel_embed @ w_rel ----------------
__global__ void __launch_bounds__(256) sgemm_small_kernel(
    const float* __restrict__ A, const float* __restrict__ B, float* __restrict__ C, int M)
{
    int n = blockIdx.x * 64 + (threadIdx.x & 63);
    int m = blockIdx.y * 4 + (threadIdx.x >> 6);
    if (m >= M || n >= D) return;
    float acc = 0.f;
    for (int k = 0; k < D; k++) acc += A[m * D + k] * B[k * D + n];
    C[m * D + n] = acc;
}

// ---------------- launch ----------------
extern "C" void kernel_launch(void* const* d_in, const int* in_sizes, int n_in,
                              void* d_out, int out_size) {
    const float* init     = (const float*)d_in[0];
    const float* rel      = (const float*)d_in[1];
    const float* rte      = (const float*)d_in[2];
    const float* evemb    = (const float*)d_in[3];
    const float* evtype   = (const float*)d_in[4];
    const float* W_role   = (const float*)d_in[5];
    const float* W_type   = (const float*)d_in[6];
    const float* W_event  = (const float*)d_in[7];
    const float* W_self   = (const float*)d_in[8];
    const float* w_in     = (const float*)d_in[9];
    const float* w_out    = (const float*)d_in[10];
    const float* w_loop   = (const float*)d_in[11];
    const float* w_rel    = (const float*)d_in[12];
    const float* loop_rel = (const float*)d_in[13];
    const float* bias     = (const float*)d_in[14];
    const int* evi        = (const int*)d_in[15];
    const int* rt         = (const int*)d_in[16];
    const int* rm         = (const int*)d_in[17];
    const int* eei        = (const int*)d_in[18];
    const int* em         = (const int*)d_in[19];
    const int* ei         = (const int*)d_in[20];
    const int* et         = (const int*)d_in[21];

    float* outx = (float*)d_out;
    float* outr = outx + (size_t)NUM_ENT * D;

    float *p_evagg, *p_evrepr, *p_entagg, *p_x0;
    bf16 *p_initH, *p_initL, *p_evtH, *p_evtL, *p_evpreH, *p_evpreL, *p_catH, *p_catL;
    bf16 *p_WtH, *p_WtL, *p_WeH, *p_WeL, *p_WsH, *p_WsL, *p_B3H, *p_B3L;
    cudaGetSymbolAddress((void**)&p_evagg,  g_ev_agg);
    cudaGetSymbolAddress((void**)&p_evrepr, g_ev_repr);
    cudaGetSymbolAddress((void**)&p_entagg, g_ent_agg);
    cudaGetSymbolAddress((void**)&p_x0,     g_x0);
    cudaGetSymbolAddress((void**)&p_initH,  g_initH);
    cudaGetSymbolAddress((void**)&p_initL,  g_initL);
    cudaGetSymbolAddress((void**)&p_evtH,   g_evtH);
    cudaGetSymbolAddress((void**)&p_evtL,   g_evtL);
    cudaGetSymbolAddress((void**)&p_evpreH, g_evpreH);
    cudaGetSymbolAddress((void**)&p_evpreL, g_evpreL);
    cudaGetSymbolAddress((void**)&p_catH,   g_catH);
    cudaGetSymbolAddress((void**)&p_catL,   g_catL);
    cudaGetSymbolAddress((void**)&p_WtH,    g_WtH);
    cudaGetSymbolAddress((void**)&p_WtL,    g_WtL);
    cudaGetSymbolAddress((void**)&p_WeH,    g_WeH);
    cudaGetSymbolAddress((void**)&p_WeL,    g_WeL);
    cudaGetSymbolAddress((void**)&p_WsH,    g_WsH);
    cudaGetSymbolAddress((void**)&p_WsL,    g_WsL);
    cudaGetSymbolAddress((void**)&p_B3H,    g_B3H);
    cudaGetSymbolAddress((void**)&p_B3L,    g_B3L);

    cudaFuncSetAttribute(mma_gemm_kernel, cudaFuncAttributeMaxDynamicSharedMemorySize, SMEM_TOT);

    // CSR build
    zero_cnt_kernel<<<128, 256>>>();
    count_edges_kernel<<<512, 256>>>(ei);
    scan_kernel<<<2, 1024>>>();
    fill_edges_kernel<<<512, 256>>>(ei, et);

    // operand conversions
    conv_split_kernel<<<NUM_ENT, 256>>>(init,   p_initH, p_initL, D,      KP2);
    conv_split_kernel<<<NUM_EVT, 256>>>(evtype, p_evtH,  p_evtL,  RT_DIM, KP1);
    conv_wt_kernel<<<D, 256>>>(W_type,  p_WtH, p_WtL, RT_DIM, KP1, KP1, 0);
    conv_wt_kernel<<<D, 256>>>(W_event, p_WeH, p_WeL, D, KP2, KP2, 0);
    conv_wt_kernel<<<D, 256>>>(W_self,  p_WsH, p_WsL, D, KP2, KP2, 0);
    conv_wt_kernel<<<D, 256>>>(w_in,    p_B3H, p_B3L, D, KP2, KP3, 0);
    conv_wt_kernel<<<D, 256>>>(w_out,   p_B3H, p_B3L, D, KP2, KP3, KP2);
    conv_wt_kernel<<<D, 256>>>(w_loop,  p_B3H, p_B3L, D, KP2, KP3, 2 * KP2);

    // EventConv
    role_proj_kernel<<<ROLE_NUM, 256>>>(rte, W_role);
    event_agg_kernel<<<NUM_EVT, 256>>>(init, evi, rt, rm);
    // E1: ev_pre = evtype @ W_type + ev_agg + evemb -> split
    mma_gemm_kernel<<<(NUM_EVT + 63) / 64, 256, SMEM_TOT>>>(
        p_evtH, p_evtL, NUM_EVT, KP1, p_WtH, p_WtL, 0, p_evagg, evemb, nullptr, nullptr,
        nullptr, p_evpreH, p_evpreL, KP2, 0);
    // E2: ev_repr = tanh(ev_pre @ W_event)
    mma_gemm_kernel<<<(NUM_EVT + 63) / 64, 256, SMEM_TOT>>>(
        p_evpreH, p_evpreL, NUM_EVT, KP2, p_WeH, p_WeL, 1, nullptr, nullptr, nullptr, nullptr,
        p_evrepr, nullptr, nullptr, 0, 0);
    ent_agg_kernel<<<NUM_ENT, 256>>>(eei, em);
    // SELF: x0 = tanh(init @ W_self + ent_agg); also split(x0 - loop_rel) -> cat seg2
    mma_gemm_kernel<<<(NUM_ENT + 63) / 64, 256, SMEM_TOT>>>(
        p_initH, p_initL, NUM_ENT, KP2, p_WsH, p_WsL, 2, p_entagg, nullptr, loop_rel, nullptr,
        p_x0, p_catH, p_catL, KP3, 2 * KP2);

    // CompGCN gathers -> cat seg0/seg1
    gather_agg_kernel<<<NUM_ENT, 256>>>(rel, 0, 0);
    gather_agg_kernel<<<NUM_ENT, 256>>>(rel, 1, KP2);
    // fused output GEMM: outx = tanh((cat @ B3)/3 + bias)
    mma_gemm_kernel<<<(NUM_ENT + 63) / 64, 256, SMEM_TOT>>>(
        p_catH, p_catL, NUM_ENT, KP3, p_B3H, p_B3L, 3, nullptr, nullptr, nullptr, bias,
        outx, nullptr, nullptr, 0, 0);

    // r = rel_embed @ w_rel (exact fp32, tiny)
    {
        dim3 grid((D + 63) / 64, (2 * NUM_RELS + 3) / 4);
        sgemm_small_kernel<<<grid, 256>>>(rel, w_rel, outr, 2 * NUM_RELS);
    }
}

// round 8
// speedup vs baseline: 1.6211x; 1.0128x over previous
#include <cuda_runtime.h>
#include <cuda_bf16.h>
#include <cstdint>
#include <math.h>

#define NUM_ENT 50000
#define NUM_RELS 200
#define D 200
#define NUM_EVT 20000
#define ROLE_NUM 20
#define RT_DIM 100
#define R_SLOTS 8
#define K_SLOTS 8
#define N_EDGES 800000
#define HALF_E 400000

#define KP1 128     // padded K for RT_DIM=100
#define KP2 224     // padded K for D=200 (7 x 32)
#define KP3 672     // concatenated K for fused output GEMM (3 x 224)

typedef __nv_bfloat16 bf16;

// ---------------- scratch (device globals; 16B-aligned for vector access) -----
__device__ __align__(16) float g_ev_agg[NUM_EVT * D];
__device__ __align__(16) float g_ev_repr[NUM_EVT * D];
__device__ __align__(16) float g_ent_agg[NUM_ENT * D];
__device__ __align__(16) float g_x0[NUM_ENT * D];
__device__ __align__(16) float g_role_proj[ROLE_NUM * D];
__device__ __align__(16) bf16  g_initH[NUM_ENT * KP2];
__device__ __align__(16) bf16  g_initL[NUM_ENT * KP2];
__device__ __align__(16) bf16  g_evtH[NUM_EVT * KP1];
__device__ __align__(16) bf16  g_evtL[NUM_EVT * KP1];
__device__ __align__(16) bf16  g_evpreH[NUM_EVT * KP2];
__device__ __align__(16) bf16  g_evpreL[NUM_EVT * KP2];
__device__ __align__(16) bf16  g_catH[(size_t)NUM_ENT * KP3];
__device__ __align__(16) bf16  g_catL[(size_t)NUM_ENT * KP3];
__device__ __align__(16) bf16  g_WtH[D * KP1];
__device__ __align__(16) bf16  g_WtL[D * KP1];
__device__ __align__(16) bf16  g_WeH[D * KP2];
__device__ __align__(16) bf16  g_WeL[D * KP2];
__device__ __align__(16) bf16  g_WsH[D * KP2];
__device__ __align__(16) bf16  g_WsL[D * KP2];
__device__ __align__(16) bf16  g_B3H[D * KP3];
__device__ __align__(16) bf16  g_B3L[D * KP3];
__device__ int   g_cnt[2 * NUM_ENT];
__device__ int   g_off[2 * (NUM_ENT + 1)];
__device__ int   g_pos[2 * NUM_ENT];
__device__ __align__(16) int2  g_edges[N_EDGES];

// ---------------- helpers ----------------
__device__ __forceinline__ uint32_t smem_to_u32(const void* p) {
    uint32_t a;
    asm("{ .reg .u64 t; cvta.to.shared.u64 t, %1; cvt.u32.u64 %0, t; }" : "=r"(a) : "l"(p));
    return a;
}
__device__ __forceinline__ void split2(float v, bf16& h, bf16& l) {
    h = __float2bfloat16(v);
    l = __float2bfloat16(v - __bfloat162float(h));
}
__device__ __forceinline__ void ldsm_x4(uint32_t* r, uint32_t addr) {
    asm volatile("ldmatrix.sync.aligned.m8n8.x4.shared.b16 {%0,%1,%2,%3}, [%4];"
        : "=r"(r[0]), "=r"(r[1]), "=r"(r[2]), "=r"(r[3]) : "r"(addr));
}
__device__ __forceinline__ void ldsm_x2(uint32_t& r0, uint32_t& r1, uint32_t addr) {
    asm volatile("ldmatrix.sync.aligned.m8n8.x2.shared.b16 {%0,%1}, [%2];"
        : "=r"(r0), "=r"(r1) : "r"(addr));
}
__device__ __forceinline__ void mma_bf16(float* c, const uint32_t* a, uint32_t b0, uint32_t b1) {
    asm volatile("mma.sync.aligned.m16n8k16.row.col.f32.bf16.bf16.f32 "
        "{%0,%1,%2,%3}, {%4,%5,%6,%7}, {%8,%9}, {%0,%1,%2,%3};"
        : "+f"(c[0]), "+f"(c[1]), "+f"(c[2]), "+f"(c[3])
        : "r"(a[0]), "r"(a[1]), "r"(a[2]), "r"(a[3]), "r"(b0), "r"(b1));
}

// ---------------- CSR build ----------------
__global__ void zero_cnt_kernel() {
    int i = blockIdx.x * blockDim.x + threadIdx.x;
    int s = gridDim.x * blockDim.x;
    for (; i < 2 * NUM_ENT; i += s) g_cnt[i] = 0;
}
__global__ void count_edges_kernel(const int* __restrict__ ei) {
    const int* dst = ei + N_EDGES;
    int i = blockIdx.x * blockDim.x + threadIdx.x;
    int s = gridDim.x * blockDim.x;
    for (; i < N_EDGES; i += s) {
        int d = dst[i];
        int seg = (i < HALF_E) ? 0 : 1;
        atomicAdd(&g_cnt[seg * NUM_ENT + d], 1);
    }
}
__global__ void scan_kernel() {
    const int CH = 49;
    int seg = blockIdx.x;
    const int* cnt = g_cnt + seg * NUM_ENT;
    int* off = g_off + seg * (NUM_ENT + 1);
    int* pos = g_pos + seg * NUM_ENT;
    __shared__ int s[1024];
    int t = threadIdx.x;
    int base = t * CH;
    int sum = 0;
    for (int j = 0; j < CH; j++) { int idx = base + j; if (idx < NUM_ENT) sum += cnt[idx]; }
    s[t] = sum;
    __syncthreads();
    for (int o = 1; o < 1024; o <<= 1) {
        int v = (t >= o) ? s[t - o] : 0;
        __syncthreads();
        s[t] += v;
        __syncthreads();
    }
    int run = s[t] - sum;
    for (int j = 0; j < CH; j++) {
        int idx = base + j;
        if (idx < NUM_ENT) { off[idx] = run; pos[idx] = run; run += cnt[idx]; }
    }
    if (t == 1023) off[NUM_ENT] = s[1023];
}
__global__ void fill_edges_kernel(const int* __restrict__ ei, const int* __restrict__ et) {
    const int* src = ei;
    const int* dst = ei + N_EDGES;
    int i = blockIdx.x * blockDim.x + threadIdx.x;
    int s = gridDim.x * blockDim.x;
    for (; i < N_EDGES; i += s) {
        int seg = (i < HALF_E) ? 0 : 1;
        int d = dst[i];
        int p = atomicAdd(&g_pos[seg * NUM_ENT + d], 1);
        g_edges[seg * HALF_E + p] = make_int2(src[i], et[i]);
    }
}

// ---------------- conversions ----------------
// flat grid-stride: src [M x K] fp32 -> split bf16 [M x Kpad] (K % 4 == 0)
__global__ void conv_split_flat(const float* __restrict__ src, bf16* __restrict__ h,
                                bf16* __restrict__ l, int M, int K, int Kpad) {
    int nq = Kpad >> 2, kq = K >> 2;
    long total = (long)M * nq;
    long stride = (long)gridDim.x * blockDim.x;
    for (long idx = (long)blockIdx.x * blockDim.x + threadIdx.x; idx < total; idx += stride) {
        int m = (int)(idx / nq), q = (int)(idx % nq);
        float4 v = make_float4(0.f, 0.f, 0.f, 0.f);
        if (q < kq) v = *(const float4*)(src + (size_t)m * K + q * 4);
        bf16 h0, l0, h1, l1, h2, l2, h3, l3;
        split2(v.x, h0, l0); split2(v.y, h1, l1);
        split2(v.z, h2, l2); split2(v.w, h3, l3);
        ushort4 hv = make_ushort4(__bfloat16_as_ushort(h0), __bfloat16_as_ushort(h1),
                                  __bfloat16_as_ushort(h2), __bfloat16_as_ushort(h3));
        ushort4 lv = make_ushort4(__bfloat16_as_ushort(l0), __bfloat16_as_ushort(l1),
                                  __bfloat16_as_ushort(l2), __bfloat16_as_ushort(l3));
        *(ushort4*)(h + (size_t)m * Kpad + q * 4) = hv;
        *(ushort4*)(l + (size_t)m * Kpad + q * 4) = lv;
    }
}
// W [K x D] -> transposed split dst[n*stride + off + k]
__global__ void conv_wt_kernel(const float* __restrict__ W, bf16* __restrict__ h,
                               bf16* __restrict__ l, int K, int Kseg, int stride, int off) {
    int n = blockIdx.x, t = threadIdx.x;
    if (t < Kseg) {
        float v = (t < K) ? W[(size_t)t * D + n] : 0.f;
        bf16 hh, ll;
        split2(v, hh, ll);
        h[(size_t)n * stride + off + t] = hh;
        l[(size_t)n * stride + off + t] = ll;
    }
}

// ---------------- EventConv pieces ----------------
__global__ void role_proj_kernel(const float* __restrict__ rte, const float* __restrict__ Wr) {
    __shared__ float row[RT_DIM];
    int r = blockIdx.x, t = threadIdx.x;
    if (t < RT_DIM) row[t] = rte[r * RT_DIM + t];
    __syncthreads();
    if (t < D) {
        float acc = 0.f;
        #pragma unroll 4
        for (int k = 0; k < RT_DIM; k++) acc += row[k] * Wr[k * D + t];
        g_role_proj[r * D + t] = acc;
    }
}
__global__ void event_agg_kernel(const float* __restrict__ init, const int* __restrict__ evi,
                                 const int* __restrict__ rt, const int* __restrict__ rm) {
    __shared__ int sIdx[R_SLOTS], sRt[R_SLOTS], sM[R_SLOTS];
    __shared__ float sden;
    int e = blockIdx.x, t = threadIdx.x;
    if (t < R_SLOTS) { sIdx[t] = evi[t * NUM_EVT + e]; sRt[t] = rt[t * NUM_EVT + e]; sM[t] = rm[t * NUM_EVT + e]; }
    __syncthreads();
    if (t == 0) {
        int s = 0;
        for (int r = 0; r < R_SLOTS; r++) s += sM[r];
        sden = 1.f / fmaxf((float)s, 1.f);
    }
    __syncthreads();
    if (t < D) {
        float acc = 0.f;
        #pragma unroll
        for (int r = 0; r < R_SLOTS; r++)
            if (sM[r]) acc += init[sIdx[r] * D + t] * g_role_proj[sRt[r] * D + t];
        g_ev_agg[e * D + t] = acc * sden;
    }
}
__global__ void ent_agg_kernel(const int* __restrict__ eei, const int* __restrict__ em) {
    __shared__ int sIdx[K_SLOTS], sM[K_SLOTS];
    __shared__ float sden;
    int i = blockIdx.x, t = threadIdx.x;
    if (t < K_SLOTS) { sIdx[t] = eei[t * NUM_ENT + i]; sM[t] = em[t * NUM_ENT + i]; }
    __syncthreads();
    if (t == 0) {
        int s = 0;
        for (int k = 0; k < K_SLOTS; k++) s += sM[k];
        sden = 1.f / fmaxf((float)s, 1.f);
    }
    __syncthreads();
    if (t < D) {
        float acc = 0.f;
        #pragma unroll
        for (int k = 0; k < K_SLOTS; k++)
            if (sM[k]) acc += g_ev_repr[sIdx[k] * D + t];
        g_ent_agg[i * D + t] = acc * sden;
    }
}
// per-dst CSR gather (both segments via blockIdx.y) -> split(mean) into g_cat
// inner loop unrolled x4 for MLP
__global__ void gather_agg_kernel(const float* __restrict__ rel) {
    int i = blockIdx.x, seg = blockIdx.y, t = threadIdx.x;
    int colOff = seg * KP2;
    const int* off = g_off + seg * (NUM_ENT + 1);
    int s0 = off[i], s1 = off[i + 1];
    int cnt = s1 - s0;
    __shared__ int2 se[256];
    float acc = 0.f;
    for (int base = s0; base < s1; base += 256) {
        int nb = min(256, s1 - base);
        if (t < nb) se[t] = g_edges[seg * HALF_E + base + t];
        __syncthreads();
        if (t < D) {
            int j = 0;
            for (; j + 4 <= nb; j += 4) {
                int2 e0 = se[j], e1 = se[j + 1], e2 = se[j + 2], e3 = se[j + 3];
                float a0 = g_x0[(size_t)e0.x * D + t] - rel[(size_t)e0.y * D + t];
                float a1 = g_x0[(size_t)e1.x * D + t] - rel[(size_t)e1.y * D + t];
                float a2 = g_x0[(size_t)e2.x * D + t] - rel[(size_t)e2.y * D + t];
                float a3 = g_x0[(size_t)e3.x * D + t] - rel[(size_t)e3.y * D + t];
                acc += (a0 + a1) + (a2 + a3);
            }
            for (; j < nb; j++) {
                int2 e = se[j];
                acc += g_x0[(size_t)e.x * D + t] - rel[(size_t)e.y * D + t];
            }
        }
        __syncthreads();
    }
    if (t < D) {
        float v = acc / fmaxf((float)cnt, 1.f);
        bf16 hh, ll;
        split2(v, hh, ll);
        g_catH[(size_t)i * KP3 + colOff + t] = hh;
        g_catL[(size_t)i * KP3 + colOff + t] = ll;
    }
}

// ---------------- warp-MMA split-bf16 GEMM: C(M x 200) = A(M x Kp) @ Bt^T -------------
// CTA tile 64 x 224 (full output width -> A read once; only 12% N padding), 8 warps 2x4
// (warp tile 32x56), BK=32, register-prefetch pipeline (single smem stage, static).
// modes: 0: v=C+add0+add1 -> split(outH/L) ; 1: outF=tanh(C)
//        2: v=tanh(C+add0) -> outF AND split(v - sub[n]) -> outH/L ; 3: outF=tanh(C/3+bias[n])
#define RST 80
#define SA_OFF_H 0
#define SA_OFF_L (64 * RST)                   // 5120
#define SB_OFF_H (2 * 64 * RST)               // 10240
#define SB_OFF_L (2 * 64 * RST + 224 * RST)   // 28160
#define SMEM_TOT (2 * 64 * RST + 2 * 224 * RST) // 46080
__global__ void __launch_bounds__(256) mma_gemm_kernel(
    const bf16* __restrict__ AH, const bf16* __restrict__ AL, int M, int Kp,
    const bf16* __restrict__ BH, const bf16* __restrict__ BL, int mode,
    const float* __restrict__ add0, const float* __restrict__ add1,
    const float* __restrict__ sub, const float* __restrict__ bias,
    float* __restrict__ outF, bf16* __restrict__ outH, bf16* __restrict__ outL,
    int sStride, int sOff)
{
    __shared__ __align__(16) unsigned char dsm[SMEM_TOT];
    uint32_t sb = smem_to_u32(dsm);
    int tid = threadIdx.x, wid = tid >> 5, lane = tid & 31;
    int wm = wid & 1, wn = wid >> 1;
    int row0 = blockIdx.x * 64;

    float acc[2][7][4];
    #pragma unroll
    for (int i = 0; i < 2; i++)
        #pragma unroll
        for (int j = 0; j < 7; j++)
            #pragma unroll
            for (int k = 0; k < 4; k++) acc[i][j][k] = 0.f;

    int ar = tid >> 2, aq = tid & 3;
    bool apred = (row0 + ar) < M;
    size_t arow = apred ? (size_t)(row0 + ar) : 0;
    int nCh = Kp >> 5;
    const uint4 Z = make_uint4(0, 0, 0, 0);

    uint4 pah, pal, pbh[4], pbl[4];
    auto load_chunk = [&](int c) {
        pah = apred ? *(const uint4*)(AH + arow * Kp + c * 32 + aq * 8) : Z;
        pal = apred ? *(const uint4*)(AL + arow * Kp + c * 32 + aq * 8) : Z;
        #pragma unroll
        for (int i = 0; i < 4; i++) {
            int v = tid + i * 256;
            int br = v >> 2, bq = v & 3;
            bool bp = (v < 896) && (br < D);
            pbh[i] = bp ? *(const uint4*)(BH + (size_t)br * Kp + c * 32 + bq * 8) : Z;
            pbl[i] = bp ? *(const uint4*)(BL + (size_t)br * Kp + c * 32 + bq * 8) : Z;
        }
    };
    auto store_chunk = [&]() {
        *(uint4*)(dsm + SA_OFF_H + ar * RST + aq * 16) = pah;
        *(uint4*)(dsm + SA_OFF_L + ar * RST + aq * 16) = pal;
        #pragma unroll
        for (int i = 0; i < 4; i++) {
            int v = tid + i * 256;
            if (v < 896) {
                int br = v >> 2, bq = v & 3;
                *(uint4*)(dsm + SB_OFF_H + br * RST + bq * 16) = pbh[i];
                *(uint4*)(dsm + SB_OFF_L + br * RST + bq * 16) = pbl[i];
            }
        }
    };

    load_chunk(0);
    for (int c = 0; c < nCh; c++) {
        store_chunk();
        __syncthreads();
        if (c + 1 < nCh) load_chunk(c + 1);   // overlaps with MMA below

        uint32_t aH = sb + SA_OFF_H, aL = sb + SA_OFF_L;
        uint32_t bH = sb + SB_OFF_H, bL = sb + SB_OFF_L;
        #pragma unroll
        for (int ks = 0; ks < 2; ks++) {
            uint32_t ahi[2][4], alo[2][4];
            int arw = wm * 32 + (lane & 15);
            int aof = ks * 32 + (lane >> 4) * 16;
            #pragma unroll
            for (int mt = 0; mt < 2; mt++) {
                uint32_t ad = (arw + mt * 16) * RST + aof;
                ldsm_x4(ahi[mt], aH + ad);
                ldsm_x4(alo[mt], aL + ad);
            }
            #pragma unroll
            for (int nt = 0; nt < 7; nt++) {
                int brw = wn * 56 + nt * 8 + (lane & 7);
                int bof = ks * 32 + (((lane >> 3) & 1) << 4);
                uint32_t bd = brw * RST + bof;
                uint32_t bh0, bh1, bl0, bl1;
                ldsm_x2(bh0, bh1, bH + bd);
                ldsm_x2(bl0, bl1, bL + bd);
                #pragma unroll
                for (int mt = 0; mt < 2; mt++) {
                    mma_bf16(acc[mt][nt], ahi[mt], bh0, bh1);
                    mma_bf16(acc[mt][nt], ahi[mt], bl0, bl1);
                    mma_bf16(acc[mt][nt], alo[mt], bh0, bh1);
                }
            }
        }
        __syncthreads();
    }

    // ---- epilogue ----
    int g = lane >> 2, tg = lane & 3;
    #pragma unroll
    for (int mt = 0; mt < 2; mt++)
        #pragma unroll
        for (int nt = 0; nt < 7; nt++) {
            int n = wn * 56 + nt * 8 + tg * 2;
            if (n >= D) continue;
            #pragma unroll
            for (int hh = 0; hh < 2; hh++) {
                int m = row0 + wm * 32 + mt * 16 + g + hh * 8;
                if (m >= M) continue;
                float d0 = acc[mt][nt][2 * hh], d1 = acc[mt][nt][2 * hh + 1];
                size_t p = (size_t)m * D + n;
                if (mode == 0) {
                    float v0 = d0 + add0[p] + add1[p];
                    float v1 = d1 + add0[p + 1] + add1[p + 1];
                    bf16 h0, l0, h1, l1;
                    split2(v0, h0, l0);
                    split2(v1, h1, l1);
                    size_t q = (size_t)m * sStride + sOff + n;
                    outH[q] = h0; outH[q + 1] = h1;
                    outL[q] = l0; outL[q + 1] = l1;
                } else if (mode == 1) {
                    *(float2*)(outF + p) = make_float2(tanhf(d0), tanhf(d1));
                } else if (mode == 2) {
                    float v0 = tanhf(d0 + add0[p]);
                    float v1 = tanhf(d1 + add0[p + 1]);
                    *(float2*)(outF + p) = make_float2(v0, v1);
                    bf16 h0, l0, h1, l1;
                    split2(v0 - sub[n], h0, l0);
                    split2(v1 - sub[n + 1], h1, l1);
                    size_t q = (size_t)m * sStride + sOff + n;
                    outH[q] = h0; outH[q + 1] = h1;
                    outL[q] = l0; outL[q + 1] = l1;
                } else {
                    *(float2*)(outF + p) = make_float2(tanhf(d0 * (1.f / 3.f) + bias[n]),
                                                        tanhf(d1 * (1.f / 3.f) + bias[n + 1]));
                }
            }
        }
}

// ---------------- small exact fp32 GEMM for r = rel_embed @ w_rel ----------------
__global__ void __launch_bounds__(256) sgemm_small_kernel(
    const float* __restrict__ A, const float* __restrict__ B, float* __restrict__ C, int M)
{
    int n = blockIdx.x * 64 + (threadIdx.x & 63);
    int m = blockIdx.y * 4 + (threadIdx.x >> 6);
    if (m >= M || n >= D) return;
    float acc = 0.f;
    for (int k = 0; k < D; k++) acc += A[m * D + k] * B[k * D + n];
    C[m * D + n] = acc;
}

// ---------------- launch ----------------
extern "C" void kernel_launch(void* const* d_in, const int* in_sizes, int n_in,
                              void* d_out, int out_size) {
    const float* init     = (const float*)d_in[0];
    const float* rel      = (const float*)d_in[1];
    const float* rte      = (const float*)d_in[2];
    const float* evemb    = (const float*)d_in[3];
    const float* evtype   = (const float*)d_in[4];
    const float* W_role   = (const float*)d_in[5];
    const float* W_type   = (const float*)d_in[6];
    const float* W_event  = (const float*)d_in[7];
    const float* W_self   = (const float*)d_in[8];
    const float* w_in     = (const float*)d_in[9];
    const float* w_out    = (const float*)d_in[10];
    const float* w_loop   = (const float*)d_in[11];
    const float* w_rel    = (const float*)d_in[12];
    const float* loop_rel = (const float*)d_in[13];
    const float* bias     = (const float*)d_in[14];
    const int* evi        = (const int*)d_in[15];
    const int* rt         = (const int*)d_in[16];
    const int* rm         = (const int*)d_in[17];
    const int* eei        = (const int*)d_in[18];
    const int* em         = (const int*)d_in[19];
    const int* ei         = (const int*)d_in[20];
    const int* et         = (const int*)d_in[21];

    float* outx = (float*)d_out;
    float* outr = outx + (size_t)NUM_ENT * D;

    float *p_evagg, *p_evrepr, *p_entagg, *p_x0;
    bf16 *p_initH, *p_initL, *p_evtH, *p_evtL, *p_evpreH, *p_evpreL, *p_catH, *p_catL;
    bf16 *p_WtH, *p_WtL, *p_WeH, *p_WeL, *p_WsH, *p_WsL, *p_B3H, *p_B3L;
    cudaGetSymbolAddress((void**)&p_evagg,  g_ev_agg);
    cudaGetSymbolAddress((void**)&p_evrepr, g_ev_repr);
    cudaGetSymbolAddress((void**)&p_entagg, g_ent_agg);
    cudaGetSymbolAddress((void**)&p_x0,     g_x0);
    cudaGetSymbolAddress((void**)&p_initH,  g_initH);
    cudaGetSymbolAddress((void**)&p_initL,  g_initL);
    cudaGetSymbolAddress((void**)&p_evtH,   g_evtH);
    cudaGetSymbolAddress((void**)&p_evtL,   g_evtL);
    cudaGetSymbolAddress((void**)&p_evpreH, g_evpreH);
    cudaGetSymbolAddress((void**)&p_evpreL, g_evpreL);
    cudaGetSymbolAddress((void**)&p_catH,   g_catH);
    cudaGetSymbolAddress((void**)&p_catL,   g_catL);
    cudaGetSymbolAddress((void**)&p_WtH,    g_WtH);
    cudaGetSymbolAddress((void**)&p_WtL,    g_WtL);
    cudaGetSymbolAddress((void**)&p_WeH,    g_WeH);
    cudaGetSymbolAddress((void**)&p_WeL,    g_WeL);
    cudaGetSymbolAddress((void**)&p_WsH,    g_WsH);
    cudaGetSymbolAddress((void**)&p_WsL,    g_WsL);
    cudaGetSymbolAddress((void**)&p_B3H,    g_B3H);
    cudaGetSymbolAddress((void**)&p_B3L,    g_B3L);

    // CSR build
    zero_cnt_kernel<<<128, 256>>>();
    count_edges_kernel<<<512, 256>>>(ei);
    scan_kernel<<<2, 1024>>>();
    fill_edges_kernel<<<512, 256>>>(ei, et);

    // operand conversions
    conv_split_flat<<<2048, 256>>>(init,   p_initH, p_initL, NUM_ENT, D,      KP2);
    conv_split_flat<<<1024, 256>>>(evtype, p_evtH,  p_evtL,  NUM_EVT, RT_DIM, KP1);
    conv_wt_kernel<<<D, 256>>>(W_type,  p_WtH, p_WtL, RT_DIM, KP1, KP1, 0);
    conv_wt_kernel<<<D, 256>>>(W_event, p_WeH, p_WeL, D, KP2, KP2, 0);
    conv_wt_kernel<<<D, 256>>>(W_self,  p_WsH, p_WsL, D, KP2, KP2, 0);
    conv_wt_kernel<<<D, 256>>>(w_in,    p_B3H, p_B3L, D, KP2, KP3, 0);
    conv_wt_kernel<<<D, 256>>>(w_out,   p_B3H, p_B3L, D, KP2, KP3, KP2);
    conv_wt_kernel<<<D, 256>>>(w_loop,  p_B3H, p_B3L, D, KP2, KP3, 2 * KP2);

    // EventConv
    role_proj_kernel<<<ROLE_NUM, 256>>>(rte, W_role);
    event_agg_kernel<<<NUM_EVT, 256>>>(init, evi, rt, rm);
    // E1: ev_pre = evtype @ W_type + ev_agg + evemb -> split
    mma_gemm_kernel<<<(NUM_EVT + 63) / 64, 256>>>(
        p_evtH, p_evtL, NUM_EVT, KP1, p_WtH, p_WtL, 0, p_evagg, evemb, nullptr, nullptr,
        nullptr, p_evpreH, p_evpreL, KP2, 0);
    // E2: ev_repr = tanh(ev_pre @ W_event)
    mma_gemm_kernel<<<(NUM_EVT + 63) / 64, 256>>>(
        p_evpreH, p_evpreL, NUM_EVT, KP2, p_WeH, p_WeL, 1, nullptr, nullptr, nullptr, nullptr,
        p_evrepr, nullptr, nullptr, 0, 0);
    ent_agg_kernel<<<NUM_ENT, 256>>>(eei, em);
    // SELF: x0 = tanh(init @ W_self + ent_agg); also split(x0 - loop_rel) -> cat seg2
    mma_gemm_kernel<<<(NUM_ENT + 63) / 64, 256>>>(
        p_initH, p_initL, NUM_ENT, KP2, p_WsH, p_WsL, 2, p_entagg, nullptr, loop_rel, nullptr,
        p_x0, p_catH, p_catL, KP3, 2 * KP2);

    // CompGCN gathers (both segments) -> cat seg0/seg1
    gather_agg_kernel<<<dim3(NUM_ENT, 2), 256>>>(rel);
    // fused output GEMM: outx = tanh((cat @ B3)/3 + bias)
    mma_gemm_kernel<<<(NUM_ENT + 63) / 64, 256>>>(
        p_catH, p_catL, NUM_ENT, KP3, p_B3H, p_B3L, 3, nullptr, nullptr, nullptr, bias,
        outx, nullptr, nullptr, 0, 0);

    // r = rel_embed @ w_rel (exact fp32, tiny)
    {
        dim3 grid((D + 63) / 64, (2 * NUM_RELS + 3) / 4);
        sgemm_small_kernel<<<grid, 256>>>(rel, w_rel, outr, 2 * NUM_RELS);
    }
}